// round 3
// baseline (speedup 1.0000x reference)
#include <cuda_runtime.h>
#include <cstdint>
#include <cstddef>

#define BATCH 16384
#define NFEAT 512
#define NUSED 256
#define NLEAF 1024
#define NCLS  100
#define NCLSP 128

#define ROWS_PER_BLK 32
#define THREADS 512
#define D_PITCH 1028          // 32 x 1028 floats  (131584 B)
#define XT_PITCH 36           // 256 x 36 floats   (36864 B)
#define MU_PITCH 34           // [2][32][34]       (fits in xT region)

// smem layout (floats):
//   sd  : [32][1028]                = 32896
//   sxT : [256][36]  (phase A)      =  9216   -> reused as smu [2][32][34]
//   sw  : [32][256]  (phase A W)    =  8192   -> reused as spt [2][32][128]
#define SMEM_FLOATS (32*D_PITCH + 256*XT_PITCH + 32*256)
#define SMEM_BYTES  (SMEM_FLOATS * 4)

__device__ int   g_sel[NUSED];
__device__ float g_x[(size_t)BATCH * NUSED];
__device__ float g_probs[NLEAF * NCLSP];

__device__ __forceinline__ void ffma2(float2 &d, float2 a, float2 b) {
    asm("fma.rn.f32x2 %0, %1, %2, %0;"
        : "+l"(reinterpret_cast<unsigned long long &>(d))
        : "l"(reinterpret_cast<unsigned long long &>(a)),
          "l"(reinterpret_cast<unsigned long long &>(b)));
}
__device__ __forceinline__ float sigm(float z) { return 1.f / (1.f + __expf(-z)); }

// ---- prep kernels ----
__global__ void k_sel(const float* __restrict__ mask) {
    int j = threadIdx.x;
    if (j < NUSED) {
        const float* row = mask + j * NFEAT;
        int s = 0;
        for (int f = 0; f < NFEAT; ++f) if (row[f] > 0.5f) { s = f; break; }
        g_sel[j] = s;
    }
}
__global__ void k_softmax(const float* __restrict__ pi) {
    int r = blockIdx.x * blockDim.x + threadIdx.x;
    if (r >= NLEAF) return;
    const float* p = pi + r * NCLS;
    float mx = p[0];
    for (int c = 1; c < NCLS; ++c) mx = fmaxf(mx, p[c]);
    float s = 0.f;
    for (int c = 0; c < NCLS; ++c) s += expf(p[c] - mx);
    float inv = 1.f / s;
    float* o = g_probs + r * NCLSP;
    for (int c = 0; c < NCLS; ++c)  o[c] = expf(p[c] - mx) * inv;
    for (int c = NCLS; c < NCLSP; ++c) o[c] = 0.f;
}
__global__ void k_gather(const float* __restrict__ feat) {
    int i = blockIdx.x * 512 + threadIdx.x;
    int row = i >> 8;
    int j   = i & 255;
    g_x[i] = feat[(size_t)row * NFEAT + g_sel[j]];
}

// ---- fused: sigmoid-GEMM (smem) -> tree (on the fly) -> mu@probs ----
__global__ void __launch_bounds__(THREADS)
k_fused(const float* __restrict__ W, const float* __restrict__ bias,
        float* __restrict__ out) {
    extern __shared__ float smem[];
    float* sd  = smem;                       // [32][1028]
    float* sxT = smem + 32 * D_PITCH;        // [256][36]  / smu [2][32][34]
    float* sw  = sxT + 256 * XT_PITCH;       // [32][256]  / spt [2][32][128]

    const int t  = threadIdx.x;
    const int m0 = blockIdx.x * ROWS_PER_BLK;

    // ---- load x tile transposed: sxT[k][row] ----
    #pragma unroll
    for (int q = 0; q < 16; ++q) {
        int e = q * THREADS + t;             // 0..8191
        int row = e >> 8, k = e & 255;
        sxT[k * XT_PITCH + row] = g_x[(size_t)(m0 + row) * NUSED + k];
    }

    // ================= Phase A: d = sigmoid(x @ W + b) -> sd =================
    const int r0 = (t >> 6) * 4;             // 8 groups * 4 rows = 32
    const int c0 = (t & 63) * 4;             // 64 groups * 4 cols = 256

    for (int nc = 0; nc < 4; ++nc) {
        const int n0 = nc * 256;
        float2 acc[2][4];
        #pragma unroll
        for (int i = 0; i < 2; ++i)
            #pragma unroll
            for (int j = 0; j < 4; ++j) acc[i][j] = make_float2(0.f, 0.f);

        for (int kc = 0; kc < 8; ++kc) {
            __syncthreads();
            // W tile [32][256]
            #pragma unroll
            for (int q = 0; q < 4; ++q) {
                int idx = q * THREADS + t;   // 0..2047 float4s
                int kr = idx >> 6, c4 = idx & 63;
                *reinterpret_cast<float4*>(&sw[kr * 256 + c4 * 4]) =
                    *reinterpret_cast<const float4*>(
                        W + (size_t)(kc * 32 + kr) * NLEAF + n0 + c4 * 4);
            }
            __syncthreads();

            #pragma unroll
            for (int kk = 0; kk < 32; ++kk) {
                float4 av = *reinterpret_cast<const float4*>(
                    &sxT[(kc * 32 + kk) * XT_PITCH + r0]);
                float4 bv = *reinterpret_cast<const float4*>(&sw[kk * 256 + c0]);
                float2 ap0 = make_float2(av.x, av.y);
                float2 ap1 = make_float2(av.z, av.w);
                float2 bd[4] = { make_float2(bv.x, bv.x), make_float2(bv.y, bv.y),
                                 make_float2(bv.z, bv.z), make_float2(bv.w, bv.w) };
                #pragma unroll
                for (int j = 0; j < 4; ++j) {
                    ffma2(acc[0][j], ap0, bd[j]);
                    ffma2(acc[1][j], ap1, bd[j]);
                }
            }
        }
        // epilogue: bias + sigmoid -> sd
        float4 bb = *reinterpret_cast<const float4*>(bias + n0 + c0);
        #pragma unroll
        for (int i = 0; i < 2; ++i) {
            float4 v0, v1;
            v0.x = sigm(acc[i][0].x + bb.x);
            v0.y = sigm(acc[i][1].x + bb.y);
            v0.z = sigm(acc[i][2].x + bb.z);
            v0.w = sigm(acc[i][3].x + bb.w);
            v1.x = sigm(acc[i][0].y + bb.x);
            v1.y = sigm(acc[i][1].y + bb.y);
            v1.z = sigm(acc[i][2].y + bb.z);
            v1.w = sigm(acc[i][3].y + bb.w);
            *reinterpret_cast<float4*>(&sd[(r0 + 2 * i)     * D_PITCH + n0 + c0]) = v0;
            *reinterpret_cast<float4*>(&sd[(r0 + 2 * i + 1) * D_PITCH + n0 + c0]) = v1;
        }
    }
    __syncthreads();

    // ================= Phase B+C: mu(chunk) -> acc += mu @ probs =============
    float* smu = sxT;   // [2][32][34]
    float* spt = sw;    // [2][32][128]

    const int cr0 = (t >> 5) * 2;            // 16 groups * 2 rows = 32
    const int cc0 = (t & 31) * 4;            // 32 groups * 4 cols = 128

    float2 acc2[4];
    #pragma unroll
    for (int j = 0; j < 4; ++j) acc2[j] = make_float2(0.f, 0.f);

    // producer for chunk c into buffer c&1
    auto produce = [&](int c) {
        int b = c & 1;
        // probs tile [32][128]
        #pragma unroll
        for (int q = 0; q < 2; ++q) {
            int idx = q * THREADS + t;       // 0..1023 float4s
            int kr = idx >> 5, c4 = idx & 31;
            *reinterpret_cast<float4*>(&spt[b * 4096 + kr * 128 + c4 * 4]) =
                *reinterpret_cast<const float4*>(
                    g_probs + (size_t)(c * 32 + kr) * NCLSP + c4 * 4);
        }
        // mu chunk: 32 rows x 8 groups of 4 leaves
        if (t < 256) {
            int row = t >> 3, g = t & 7;
            int L0 = c * 32 + g * 4;
            const float* dr = sd + row * D_PITCH;
            float p = 1.f;
            #pragma unroll
            for (int k = 0; k < 8; ++k) {
                int node = (1 << k) + (L0 >> (10 - k));
                float v  = dr[node];
                p *= ((L0 >> (9 - k)) & 1) ? (1.f - v) : v;
            }
            float v8  = dr[256 + (L0 >> 2)];
            float v9a = dr[512 + (L0 >> 1)];
            float v9b = dr[512 + (L0 >> 1) + 1];
            float* mb = smu + b * 1088 + row;   // [kk][34] + row
            int kkb = g * 4;
            mb[(kkb + 0) * MU_PITCH] = p * v8 * v9a;
            mb[(kkb + 1) * MU_PITCH] = p * v8 * (1.f - v9a);
            mb[(kkb + 2) * MU_PITCH] = p * (1.f - v8) * v9b;
            mb[(kkb + 3) * MU_PITCH] = p * (1.f - v8) * (1.f - v9b);
        }
    };

    produce(0);
    for (int c = 0; c < 32; ++c) {
        __syncthreads();                     // buffer c ready; buffer (c+1)&1 free
        if (c + 1 < 32) produce(c + 1);
        int b = c & 1;
        #pragma unroll
        for (int kk = 0; kk < 32; ++kk) {
            float2 a2 = *reinterpret_cast<const float2*>(
                &smu[b * 1088 + kk * MU_PITCH + cr0]);
            float4 bv = *reinterpret_cast<const float4*>(
                &spt[b * 4096 + kk * 128 + cc0]);
            float2 bd[4] = { make_float2(bv.x, bv.x), make_float2(bv.y, bv.y),
                             make_float2(bv.z, bv.z), make_float2(bv.w, bv.w) };
            #pragma unroll
            for (int j = 0; j < 4; ++j) ffma2(acc2[j], a2, bd[j]);
        }
    }

    // epilogue: store cols < 100
    if (cc0 < NCLS) {
        float4 v0 = make_float4(acc2[0].x, acc2[1].x, acc2[2].x, acc2[3].x);
        float4 v1 = make_float4(acc2[0].y, acc2[1].y, acc2[2].y, acc2[3].y);
        *reinterpret_cast<float4*>(out + (size_t)(m0 + cr0)     * NCLS + cc0) = v0;
        *reinterpret_cast<float4*>(out + (size_t)(m0 + cr0 + 1) * NCLS + cc0) = v1;
    }
}

extern "C" void kernel_launch(void* const* d_in, const int* in_sizes, int n_in,
                              void* d_out, int out_size) {
    const float* feat = (const float*)d_in[0];
    const float* mask = (const float*)d_in[1];
    const float* W    = (const float*)d_in[2];
    const float* b    = (const float*)d_in[3];
    const float* pi   = (const float*)d_in[4];
    float* out = (float*)d_out;
    (void)in_sizes; (void)n_in; (void)out_size;

    cudaFuncSetAttribute(k_fused, cudaFuncAttributeMaxDynamicSharedMemorySize,
                         SMEM_BYTES);

    k_sel<<<1, 256>>>(mask);
    k_softmax<<<4, 256>>>(pi);
    k_gather<<<(BATCH * NUSED) / 512, 512>>>(feat);
    k_fused<<<BATCH / ROWS_PER_BLK, THREADS, SMEM_BYTES>>>(W, b, out);
}

// round 5
// speedup vs baseline: 2.0756x; 2.0756x over previous
#include <cuda_runtime.h>
#include <cuda_bf16.h>
#include <cstdint>
#include <cstddef>

#define BATCH 16384
#define NFEAT 512
#define NUSED 256
#define NLEAF 1024
#define NCLS  100
#define NCLSP 128

// ---------------- device scratch ----------------
__device__ int   g_sel[NUSED];
__device__ float g_d[(size_t)BATCH * NLEAF];                  // fp32 d (tree input)
__device__ __nv_bfloat16 g_xh[(size_t)BATCH * NUSED];         // x hi
__device__ __nv_bfloat16 g_xl[(size_t)BATCH * NUSED];         // x lo
__device__ __nv_bfloat16 g_wh[NLEAF * NUSED];                 // W^T hi  [n][k]
__device__ __nv_bfloat16 g_wl[NLEAF * NUSED];                 // W^T lo
__device__ __nv_bfloat16 g_muh[(size_t)BATCH * NLEAF];        // mu hi
__device__ __nv_bfloat16 g_mul[(size_t)BATCH * NLEAF];        // mu lo
__device__ __nv_bfloat16 g_ph[NCLSP * NLEAF];                 // probs^T hi [c][L]
__device__ __nv_bfloat16 g_pl[NCLSP * NLEAF];                 // probs^T lo

// ---------------- helpers ----------------
__device__ __forceinline__ uint32_t smem_u32(const void* p) {
    uint32_t a;
    asm("{ .reg .u64 t; cvta.to.shared.u64 t, %1; cvt.u32.u64 %0, t; }" : "=r"(a) : "l"(p));
    return a;
}
__device__ __forceinline__ void ldsm4(uint32_t r[4], uint32_t addr) {
    asm volatile("ldmatrix.sync.aligned.m8n8.x4.shared.b16 {%0,%1,%2,%3}, [%4];"
                 : "=r"(r[0]), "=r"(r[1]), "=r"(r[2]), "=r"(r[3]) : "r"(addr));
}
__device__ __forceinline__ void mma16816(float c[4], const uint32_t a[4], const uint32_t b[2]) {
    asm volatile("mma.sync.aligned.m16n8k16.row.col.f32.bf16.bf16.f32 "
                 "{%0,%1,%2,%3}, {%4,%5,%6,%7}, {%8,%9}, {%0,%1,%2,%3};"
                 : "+f"(c[0]), "+f"(c[1]), "+f"(c[2]), "+f"(c[3])
                 : "r"(a[0]), "r"(a[1]), "r"(a[2]), "r"(a[3]), "r"(b[0]), "r"(b[1]));
}
__device__ __forceinline__ float sigm(float z) { return 1.f / (1.f + __expf(-z)); }

// smem tile pitch: 40 bf16 = 80 B (5 x 16B, odd -> conflict-free ldmatrix)
#define PITCH_B 80

// ---------------- prep kernels ----------------
__global__ void k_sel(const float* __restrict__ mask) {
    int j = threadIdx.x;
    if (j < NUSED) {
        const float* row = mask + j * NFEAT;
        int s = 0;
        for (int f = 0; f < NFEAT; ++f) if (row[f] > 0.5f) { s = f; break; }
        g_sel[j] = s;
    }
}

// probs = softmax(pi), stored transposed bf16 hi/lo: g_ph[c][L]; pad c in [100,128) with 0
__global__ void k_softmax(const float* __restrict__ pi) {
    int r = blockIdx.x * blockDim.x + threadIdx.x;
    if (r >= NLEAF) return;
    const float* p = pi + r * NCLS;
    float mx = p[0];
    for (int c = 1; c < NCLS; ++c) mx = fmaxf(mx, p[c]);
    float s = 0.f;
    for (int c = 0; c < NCLS; ++c) s += expf(p[c] - mx);
    float inv = 1.f / s;
    for (int c = 0; c < NCLS; ++c) {
        float v = expf(p[c] - mx) * inv;
        __nv_bfloat16 hi = __float2bfloat16(v);
        __nv_bfloat16 lo = __float2bfloat16(v - __bfloat162float(hi));
        g_ph[c * NLEAF + r] = hi;
        g_pl[c * NLEAF + r] = lo;
    }
    for (int c = NCLS; c < NCLSP; ++c) {
        g_ph[c * NLEAF + r] = __float2bfloat16(0.f);
        g_pl[c * NLEAF + r] = __float2bfloat16(0.f);
    }
}

// W [k=256][n=1024] fp32 -> transposed bf16 hi/lo [n][k]
__global__ void k_wprep(const float* __restrict__ W) {
    int idx = blockIdx.x * 256 + threadIdx.x;   // 0 .. 262143
    int n = idx >> 8, k = idx & 255;
    float v = W[(size_t)k * NLEAF + n];
    __nv_bfloat16 hi = __float2bfloat16(v);
    __nv_bfloat16 lo = __float2bfloat16(v - __bfloat162float(hi));
    g_wh[n * NUSED + k] = hi;
    g_wl[n * NUSED + k] = lo;
}

// x[b,j] = feat[b, sel[j]] split to bf16 hi/lo
__global__ void k_gather(const float* __restrict__ feat) {
    int i = blockIdx.x * 512 + threadIdx.x;
    int row = i >> 8, j = i & 255;
    float v = feat[(size_t)row * NFEAT + g_sel[j]];
    __nv_bfloat16 hi = __float2bfloat16(v);
    __nv_bfloat16 lo = __float2bfloat16(v - __bfloat162float(hi));
    g_xh[i] = hi;
    g_xl[i] = lo;
}

// ---------------- GEMM1: d = sigmoid(x @ W + b), HMMA bf16 3-pass ----------------
// block: 128 (M) x 128 (N), 256 thr = 8 warps (2M x 4N), warp tile 64x32
__global__ void __launch_bounds__(256, 2)
k_gemm1(const float* __restrict__ bias) {
    __shared__ __align__(16) uint8_t sAhi[128 * PITCH_B];
    __shared__ __align__(16) uint8_t sAlo[128 * PITCH_B];
    __shared__ __align__(16) uint8_t sBhi[128 * PITCH_B];
    __shared__ __align__(16) uint8_t sBlo[128 * PITCH_B];

    const int t = threadIdx.x;
    const int lane = t & 31, wid = t >> 5;
    const int warpM = wid >> 2, warpN = wid & 3;
    const int m0 = blockIdx.x * 128;
    const int n0 = blockIdx.y * 128;

    const uint32_t uAhi = smem_u32(sAhi), uAlo = smem_u32(sAlo);
    const uint32_t uBhi = smem_u32(sBhi), uBlo = smem_u32(sBlo);

    // ldmatrix lane offsets (bytes)
    const uint32_t aOff = (uint32_t)((lane & 15) * PITCH_B + (lane >> 4) * 16);
    const uint32_t bOff = (uint32_t)(((lane & 7) + ((lane >> 4) << 3)) * PITCH_B
                                     + ((lane >> 3) & 1) * 16);

    float acc[4][4][4];
    #pragma unroll
    for (int i = 0; i < 4; ++i)
        #pragma unroll
        for (int j = 0; j < 4; ++j)
            #pragma unroll
            for (int q = 0; q < 4; ++q) acc[i][j][q] = 0.f;

    for (int kc = 0; kc < 8; ++kc) {
        if (kc) __syncthreads();
        // A chunk: 128 rows x 32 k (hi & lo), uint4 = 8 bf16
        #pragma unroll
        for (int q = 0; q < 2; ++q) {
            int idx = q * 256 + t;              // 0..511
            int row = idx >> 2, c4 = idx & 3;
            size_t g = (size_t)(m0 + row) * NUSED + kc * 32 + c4 * 8;
            uint32_t d = (uint32_t)(row * PITCH_B + c4 * 16);
            *reinterpret_cast<uint4*>(sAhi + d) = *reinterpret_cast<const uint4*>(g_xh + g);
            *reinterpret_cast<uint4*>(sAlo + d) = *reinterpret_cast<const uint4*>(g_xl + g);
        }
        // B chunk: 128 n-rows x 32 k
        #pragma unroll
        for (int q = 0; q < 2; ++q) {
            int idx = q * 256 + t;
            int row = idx >> 2, c4 = idx & 3;
            size_t g = (size_t)(n0 + row) * NUSED + kc * 32 + c4 * 8;
            uint32_t d = (uint32_t)(row * PITCH_B + c4 * 16);
            *reinterpret_cast<uint4*>(sBhi + d) = *reinterpret_cast<const uint4*>(g_wh + g);
            *reinterpret_cast<uint4*>(sBlo + d) = *reinterpret_cast<const uint4*>(g_wl + g);
        }
        __syncthreads();

        #pragma unroll
        for (int ks = 0; ks < 2; ++ks) {
            const uint32_t kb = ks * 32;
            #pragma unroll
            for (int pass = 0; pass < 3; ++pass) {
                const uint32_t uA = (pass == 1) ? uAlo : uAhi;
                const uint32_t uB = (pass == 2) ? uBlo : uBhi;
                uint32_t a[4][4];
                #pragma unroll
                for (int mf = 0; mf < 4; ++mf)
                    ldsm4(a[mf], uA + (uint32_t)(warpM * 64 + mf * 16) * PITCH_B + aOff + kb);
                uint32_t b[2][4];
                #pragma unroll
                for (int p = 0; p < 2; ++p)
                    ldsm4(b[p], uB + (uint32_t)(warpN * 32 + p * 16) * PITCH_B + bOff + kb);
                #pragma unroll
                for (int mf = 0; mf < 4; ++mf)
                    #pragma unroll
                    for (int nf = 0; nf < 4; ++nf)
                        mma16816(acc[mf][nf], a[mf], &b[nf >> 1][(nf & 1) * 2]);
            }
        }
    }

    // epilogue: bias + sigmoid -> g_d (fp32)
    #pragma unroll
    for (int mf = 0; mf < 4; ++mf) {
        int row = m0 + warpM * 64 + mf * 16 + (lane >> 2);
        #pragma unroll
        for (int nf = 0; nf < 4; ++nf) {
            int col = n0 + warpN * 32 + nf * 8 + (lane & 3) * 2;
            float2 bb = *reinterpret_cast<const float2*>(bias + col);
            float2 v0, v1;
            v0.x = sigm(acc[mf][nf][0] + bb.x);
            v0.y = sigm(acc[mf][nf][1] + bb.y);
            v1.x = sigm(acc[mf][nf][2] + bb.x);
            v1.y = sigm(acc[mf][nf][3] + bb.y);
            *reinterpret_cast<float2*>(g_d + (size_t)row * NLEAF + col) = v0;
            *reinterpret_cast<float2*>(g_d + (size_t)(row + 8) * NLEAF + col) = v1;
        }
    }
}

// ---------------- tree: mu (bf16 hi/lo) from d ----------------
__global__ void __launch_bounds__(256) k_tree() {
    __shared__ float ds[8][NLEAF];
    const int t = threadIdx.x;
    const size_t base = (size_t)blockIdx.x * 8 * NLEAF;

    const float4* src = reinterpret_cast<const float4*>(g_d + base);
    float4* s4 = reinterpret_cast<float4*>(&ds[0][0]);
    #pragma unroll
    for (int q = 0; q < 8; ++q) s4[q * 256 + t] = src[q * 256 + t];
    __syncthreads();

    const int r  = t >> 5;
    const int l0 = t & 31;
    const float* dr = ds[r];
    const size_t ob = base + (size_t)r * NLEAF;

    for (int i = 0; i < 32; ++i) {
        int L = l0 + (i << 5);
        float m = 1.f;
        #pragma unroll
        for (int k = 0; k < 10; ++k) {
            int node = (1 << k) + (L >> (10 - k));
            float v  = dr[node];
            m *= ((L >> (9 - k)) & 1) ? (1.f - v) : v;
        }
        __nv_bfloat16 hi = __float2bfloat16(m);
        __nv_bfloat16 lo = __float2bfloat16(m - __bfloat162float(hi));
        g_muh[ob + L] = hi;
        g_mul[ob + L] = lo;
    }
}

// ---------------- GEMM2: out = mu @ probs, HMMA bf16 3-pass ----------------
// block: 64 (M) x 128 (N), 256 thr = 8 warps (2M x 4N), warp tile 32x32
__global__ void __launch_bounds__(256, 2)
k_gemm2(float* __restrict__ out) {
    __shared__ __align__(16) uint8_t sAhi[64 * PITCH_B];
    __shared__ __align__(16) uint8_t sAlo[64 * PITCH_B];
    __shared__ __align__(16) uint8_t sBhi[128 * PITCH_B];
    __shared__ __align__(16) uint8_t sBlo[128 * PITCH_B];

    const int t = threadIdx.x;
    const int lane = t & 31, wid = t >> 5;
    const int warpM = wid >> 2, warpN = wid & 3;
    const int m0 = blockIdx.x * 64;

    const uint32_t uAhi = smem_u32(sAhi), uAlo = smem_u32(sAlo);
    const uint32_t uBhi = smem_u32(sBhi), uBlo = smem_u32(sBlo);

    const uint32_t aOff = (uint32_t)((lane & 15) * PITCH_B + (lane >> 4) * 16);
    const uint32_t bOff = (uint32_t)(((lane & 7) + ((lane >> 4) << 3)) * PITCH_B
                                     + ((lane >> 3) & 1) * 16);

    float acc[2][4][4];
    #pragma unroll
    for (int i = 0; i < 2; ++i)
        #pragma unroll
        for (int j = 0; j < 4; ++j)
            #pragma unroll
            for (int q = 0; q < 4; ++q) acc[i][j][q] = 0.f;

    for (int kc = 0; kc < 32; ++kc) {       // K = 1024 in 32-chunks
        if (kc) __syncthreads();
        // A chunk: 64 rows x 32 k
        {
            int row = t >> 2, c4 = t & 3;
            size_t g = (size_t)(m0 + row) * NLEAF + kc * 32 + c4 * 8;
            uint32_t d = (uint32_t)(row * PITCH_B + c4 * 16);
            *reinterpret_cast<uint4*>(sAhi + d) = *reinterpret_cast<const uint4*>(g_muh + g);
            *reinterpret_cast<uint4*>(sAlo + d) = *reinterpret_cast<const uint4*>(g_mul + g);
        }
        // B chunk: 128 rows x 32 k
        #pragma unroll
        for (int q = 0; q < 2; ++q) {
            int idx = q * 256 + t;
            int row = idx >> 2, c4 = idx & 3;
            size_t g = (size_t)row * NLEAF + kc * 32 + c4 * 8;
            uint32_t d = (uint32_t)(row * PITCH_B + c4 * 16);
            *reinterpret_cast<uint4*>(sBhi + d) = *reinterpret_cast<const uint4*>(g_ph + g);
            *reinterpret_cast<uint4*>(sBlo + d) = *reinterpret_cast<const uint4*>(g_pl + g);
        }
        __syncthreads();

        #pragma unroll
        for (int ks = 0; ks < 2; ++ks) {
            const uint32_t kb = ks * 32;
            #pragma unroll
            for (int pass = 0; pass < 3; ++pass) {
                const uint32_t uA = (pass == 1) ? uAlo : uAhi;
                const uint32_t uB = (pass == 2) ? uBlo : uBhi;
                uint32_t a[2][4];
                #pragma unroll
                for (int mf = 0; mf < 2; ++mf)
                    ldsm4(a[mf], uA + (uint32_t)(warpM * 32 + mf * 16) * PITCH_B + aOff + kb);
                uint32_t b[2][4];
                #pragma unroll
                for (int p = 0; p < 2; ++p)
                    ldsm4(b[p], uB + (uint32_t)(warpN * 32 + p * 16) * PITCH_B + bOff + kb);
                #pragma unroll
                for (int mf = 0; mf < 2; ++mf)
                    #pragma unroll
                    for (int nf = 0; nf < 4; ++nf)
                        mma16816(acc[mf][nf], a[mf], &b[nf >> 1][(nf & 1) * 2]);
            }
        }
    }

    // epilogue: store cols < 100
    #pragma unroll
    for (int mf = 0; mf < 2; ++mf) {
        int row = m0 + warpM * 32 + mf * 16 + (lane >> 2);
        #pragma unroll
        for (int nf = 0; nf < 4; ++nf) {
            int col = warpN * 32 + nf * 8 + (lane & 3) * 2;
            if (col < NCLS) {
                float2 v0 = make_float2(acc[mf][nf][0], acc[mf][nf][1]);
                float2 v1 = make_float2(acc[mf][nf][2], acc[mf][nf][3]);
                *reinterpret_cast<float2*>(out + (size_t)row * NCLS + col) = v0;
                *reinterpret_cast<float2*>(out + (size_t)(row + 8) * NCLS + col) = v1;
            }
        }
    }
}

// ---------------- launch ----------------
extern "C" void kernel_launch(void* const* d_in, const int* in_sizes, int n_in,
                              void* d_out, int out_size) {
    const float* feat = (const float*)d_in[0];
    const float* mask = (const float*)d_in[1];
    const float* W    = (const float*)d_in[2];
    const float* b    = (const float*)d_in[3];
    const float* pi   = (const float*)d_in[4];
    float* out = (float*)d_out;
    (void)in_sizes; (void)n_in; (void)out_size;

    k_sel<<<1, 256>>>(mask);
    k_softmax<<<4, 256>>>(pi);
    k_wprep<<<(NLEAF * NUSED) / 256, 256>>>(W);
    k_gather<<<(BATCH * NUSED) / 512, 512>>>(feat);
    k_gemm1<<<dim3(BATCH / 128, NLEAF / 128), 256>>>(b);
    k_tree<<<BATCH / 8, 256>>>();
    k_gemm2<<<BATCH / 64, 256>>>(out);
}

// round 6
// speedup vs baseline: 2.4167x; 1.1643x over previous
#include <cuda_runtime.h>
#include <cuda_bf16.h>
#include <cstdint>
#include <cstddef>

#define BATCH 16384
#define NFEAT 512
#define NUSED 256
#define NLEAF 1024
#define NCLS  100
#define NCLSP 128

// ---------------- device scratch ----------------
__device__ int   g_sel[NUSED];
__device__ float g_d[(size_t)BATCH * NLEAF];                  // fp32 d (tree input)
__device__ __nv_bfloat16 g_xh[(size_t)BATCH * NUSED];         // x hi
__device__ __nv_bfloat16 g_xl[(size_t)BATCH * NUSED];         // x lo
__device__ __nv_bfloat16 g_wh[NLEAF * NUSED];                 // W^T hi  [n][k]
__device__ __nv_bfloat16 g_wl[NLEAF * NUSED];                 // W^T lo
__device__ __nv_bfloat16 g_muh[(size_t)BATCH * NLEAF];        // mu hi
__device__ __nv_bfloat16 g_mul[(size_t)BATCH * NLEAF];        // mu lo
__device__ __nv_bfloat16 g_ph[NCLSP * NLEAF];                 // probs^T hi [c][L]
__device__ __nv_bfloat16 g_pl[NCLSP * NLEAF];                 // probs^T lo

// ---------------- helpers ----------------
__device__ __forceinline__ uint32_t smem_u32(const void* p) {
    uint32_t a;
    asm("{ .reg .u64 t; cvta.to.shared.u64 t, %1; cvt.u32.u64 %0, t; }" : "=r"(a) : "l"(p));
    return a;
}
__device__ __forceinline__ void ldsm4(uint32_t r[4], uint32_t addr) {
    asm volatile("ldmatrix.sync.aligned.m8n8.x4.shared.b16 {%0,%1,%2,%3}, [%4];"
                 : "=r"(r[0]), "=r"(r[1]), "=r"(r[2]), "=r"(r[3]) : "r"(addr));
}
__device__ __forceinline__ void mma16816(float c[4], const uint32_t a[4], const uint32_t b[2]) {
    asm volatile("mma.sync.aligned.m16n8k16.row.col.f32.bf16.bf16.f32 "
                 "{%0,%1,%2,%3}, {%4,%5,%6,%7}, {%8,%9}, {%0,%1,%2,%3};"
                 : "+f"(c[0]), "+f"(c[1]), "+f"(c[2]), "+f"(c[3])
                 : "r"(a[0]), "r"(a[1]), "r"(a[2]), "r"(a[3]), "r"(b[0]), "r"(b[1]));
}
__device__ __forceinline__ void cp16(uint32_t smem_dst, const void* gptr) {
    asm volatile("cp.async.cg.shared.global [%0], [%1], 16;"
                 :: "r"(smem_dst), "l"(gptr));
}
#define CP_COMMIT() asm volatile("cp.async.commit_group;" ::: "memory")
#define CP_WAIT0()  asm volatile("cp.async.wait_group 0;" ::: "memory")

__device__ __forceinline__ float sigm(float z) { return 1.f / (1.f + __expf(-z)); }

// smem tile pitch: 40 bf16 = 80 B (5 x 16B -> conflict-free ldmatrix phases)
#define PITCH_B 80

// ---------------- prep kernels ----------------
__global__ void k_sel(const float* __restrict__ mask) {
    int j = threadIdx.x;
    if (j < NUSED) {
        const float* row = mask + j * NFEAT;
        int s = 0;
        for (int f = 0; f < NFEAT; ++f) if (row[f] > 0.5f) { s = f; break; }
        g_sel[j] = s;
    }
}

__global__ void k_softmax(const float* __restrict__ pi) {
    int r = blockIdx.x * blockDim.x + threadIdx.x;
    if (r >= NLEAF) return;
    const float* p = pi + r * NCLS;
    float mx = p[0];
    for (int c = 1; c < NCLS; ++c) mx = fmaxf(mx, p[c]);
    float s = 0.f;
    for (int c = 0; c < NCLS; ++c) s += expf(p[c] - mx);
    float inv = 1.f / s;
    for (int c = 0; c < NCLS; ++c) {
        float v = expf(p[c] - mx) * inv;
        __nv_bfloat16 hi = __float2bfloat16(v);
        __nv_bfloat16 lo = __float2bfloat16(v - __bfloat162float(hi));
        g_ph[c * NLEAF + r] = hi;
        g_pl[c * NLEAF + r] = lo;
    }
    for (int c = NCLS; c < NCLSP; ++c) {
        g_ph[c * NLEAF + r] = __float2bfloat16(0.f);
        g_pl[c * NLEAF + r] = __float2bfloat16(0.f);
    }
}

__global__ void k_wprep(const float* __restrict__ W) {
    int idx = blockIdx.x * 256 + threadIdx.x;
    int n = idx >> 8, k = idx & 255;
    float v = W[(size_t)k * NLEAF + n];
    __nv_bfloat16 hi = __float2bfloat16(v);
    __nv_bfloat16 lo = __float2bfloat16(v - __bfloat162float(hi));
    g_wh[n * NUSED + k] = hi;
    g_wl[n * NUSED + k] = lo;
}

__global__ void k_gather(const float* __restrict__ feat) {
    int i = blockIdx.x * 512 + threadIdx.x;
    int row = i >> 8, j = i & 255;
    float v = feat[(size_t)row * NFEAT + g_sel[j]];
    __nv_bfloat16 hi = __float2bfloat16(v);
    __nv_bfloat16 lo = __float2bfloat16(v - __bfloat162float(hi));
    g_xh[i] = hi;
    g_xl[i] = lo;
}

// ---------------- GEMM1: d = sigmoid(x @ W + b) ----------------
// block 128x128, 8 warps (2M x 4N), warp 64x32, K-chunks of 32, cp.async double buffer
// dyn smem per stage: Ahi 10240 | Alo 10240 | Bhi 10240 | Blo 10240 = 40960; x2 stages
#define G1_STAGE 40960
#define G1_SMEM  (2 * G1_STAGE)

__global__ void __launch_bounds__(256, 2)
k_gemm1(const float* __restrict__ bias) {
    extern __shared__ __align__(16) uint8_t smem[];
    const uint32_t sb = smem_u32(smem);

    const int t = threadIdx.x;
    const int lane = t & 31, wid = t >> 5;
    const int warpM = wid >> 2, warpN = wid & 3;
    const int m0 = blockIdx.x * 128;
    const int n0 = blockIdx.y * 128;

    const uint32_t aOff = (uint32_t)((lane & 15) * PITCH_B + (lane >> 4) * 16);
    const uint32_t bOff = (uint32_t)(((lane & 7) + ((lane >> 4) << 3)) * PITCH_B
                                     + ((lane >> 3) & 1) * 16);

    float acc[4][4][4];
    #pragma unroll
    for (int i = 0; i < 4; ++i)
        #pragma unroll
        for (int j = 0; j < 4; ++j)
            #pragma unroll
            for (int q = 0; q < 4; ++q) acc[i][j][q] = 0.f;

    auto prefetch = [&](int kc, int s) {
        const uint32_t base = sb + (uint32_t)s * G1_STAGE;
        #pragma unroll
        for (int q = 0; q < 2; ++q) {
            int idx = q * 256 + t;              // 0..511
            int row = idx >> 2, c4 = idx & 3;
            uint32_t d = (uint32_t)(row * PITCH_B + c4 * 16);
            size_t ga = (size_t)(m0 + row) * NUSED + kc * 32 + c4 * 8;
            cp16(base +         d, g_xh + ga);
            cp16(base + 10240 + d, g_xl + ga);
            size_t gb = (size_t)(n0 + row) * NUSED + kc * 32 + c4 * 8;
            cp16(base + 20480 + d, g_wh + gb);
            cp16(base + 30720 + d, g_wl + gb);
        }
    };

    prefetch(0, 0);
    CP_COMMIT();

    for (int kc = 0; kc < 8; ++kc) {
        CP_WAIT0();
        __syncthreads();
        if (kc + 1 < 8) { prefetch(kc + 1, (kc + 1) & 1); CP_COMMIT(); }

        const uint32_t base = sb + (uint32_t)(kc & 1) * G1_STAGE;
        #pragma unroll
        for (int ks = 0; ks < 2; ++ks) {
            const uint32_t kb = ks * 32;
            #pragma unroll
            for (int pass = 0; pass < 3; ++pass) {
                const uint32_t uA = base + ((pass == 1) ? 10240u : 0u);
                const uint32_t uB = base + 20480u + ((pass == 2) ? 10240u : 0u);
                uint32_t a[4][4];
                #pragma unroll
                for (int mf = 0; mf < 4; ++mf)
                    ldsm4(a[mf], uA + (uint32_t)(warpM * 64 + mf * 16) * PITCH_B + aOff + kb);
                uint32_t b[2][4];
                #pragma unroll
                for (int p = 0; p < 2; ++p)
                    ldsm4(b[p], uB + (uint32_t)(warpN * 32 + p * 16) * PITCH_B + bOff + kb);
                #pragma unroll
                for (int mf = 0; mf < 4; ++mf)
                    #pragma unroll
                    for (int nf = 0; nf < 4; ++nf)
                        mma16816(acc[mf][nf], a[mf], &b[nf >> 1][(nf & 1) * 2]);
            }
        }
    }

    // epilogue: bias + sigmoid -> g_d (fp32)
    #pragma unroll
    for (int mf = 0; mf < 4; ++mf) {
        int row = m0 + warpM * 64 + mf * 16 + (lane >> 2);
        #pragma unroll
        for (int nf = 0; nf < 4; ++nf) {
            int col = n0 + warpN * 32 + nf * 8 + (lane & 3) * 2;
            float2 bb = *reinterpret_cast<const float2*>(bias + col);
            float2 v0, v1;
            v0.x = sigm(acc[mf][nf][0] + bb.x);
            v0.y = sigm(acc[mf][nf][1] + bb.y);
            v1.x = sigm(acc[mf][nf][2] + bb.x);
            v1.y = sigm(acc[mf][nf][3] + bb.y);
            *reinterpret_cast<float2*>(g_d + (size_t)row * NLEAF + col) = v0;
            *reinterpret_cast<float2*>(g_d + (size_t)(row + 8) * NLEAF + col) = v1;
        }
    }
}

// ---------------- tree: mu (bf16 hi/lo) from d, 4-leaf groups ----------------
__global__ void __launch_bounds__(256) k_tree() {
    __shared__ float ds[8][NLEAF];
    const int t = threadIdx.x;
    const size_t base = (size_t)blockIdx.x * 8 * NLEAF;

    const float4* src = reinterpret_cast<const float4*>(g_d + base);
    float4* s4 = reinterpret_cast<float4*>(&ds[0][0]);
    #pragma unroll
    for (int q = 0; q < 8; ++q) s4[q * 256 + t] = src[q * 256 + t];
    __syncthreads();

    const int r  = t >> 5;
    const int l0 = t & 31;
    const float* dr = ds[r];
    const size_t ob = base + (size_t)r * NLEAF;

    #pragma unroll
    for (int i = 0; i < 8; ++i) {
        int g = i * 32 + l0;
        int L0 = g * 4;
        // shared prefix: levels 0..7 identical for the 4 leaves
        float p = 1.f;
        #pragma unroll
        for (int k = 0; k < 8; ++k) {
            int node = (1 << k) + (L0 >> (10 - k));
            float v  = dr[node];
            p *= ((L0 >> (9 - k)) & 1) ? (1.f - v) : v;
        }
        float v8  = dr[256 + (L0 >> 2)];
        float v9a = dr[512 + (L0 >> 1)];
        float v9b = dr[512 + (L0 >> 1) + 1];
        float pv8  = p * v8;
        float pn8  = p - pv8;               // p * (1 - v8)
        float m0 = pv8 * v9a;
        float m1 = pv8 - m0;                // pv8 * (1 - v9a)
        float m2 = pn8 * v9b;
        float m3 = pn8 - m2;                // pn8 * (1 - v9b)

        __nv_bfloat16 h0 = __float2bfloat16(m0), h1 = __float2bfloat16(m1);
        __nv_bfloat16 h2 = __float2bfloat16(m2), h3 = __float2bfloat16(m3);
        __nv_bfloat162 hp0 = __nv_bfloat162(h0, h1), hp1 = __nv_bfloat162(h2, h3);
        __nv_bfloat162 lp0 = __nv_bfloat162(
            __float2bfloat16(m0 - __bfloat162float(h0)),
            __float2bfloat16(m1 - __bfloat162float(h1)));
        __nv_bfloat162 lp1 = __nv_bfloat162(
            __float2bfloat16(m2 - __bfloat162float(h2)),
            __float2bfloat16(m3 - __bfloat162float(h3)));

        uint2 hu, lu;
        hu.x = *reinterpret_cast<uint32_t*>(&hp0);
        hu.y = *reinterpret_cast<uint32_t*>(&hp1);
        lu.x = *reinterpret_cast<uint32_t*>(&lp0);
        lu.y = *reinterpret_cast<uint32_t*>(&lp1);
        *reinterpret_cast<uint2*>(g_muh + ob + L0) = hu;
        *reinterpret_cast<uint2*>(g_mul + ob + L0) = lu;
    }
}

// ---------------- GEMM2: out = mu @ probs ----------------
// block 64x128, 8 warps (2M x 4N), warp 32x32, K-chunks of 32, cp.async double buffer
// dyn smem per stage: Ahi 5120 | Alo 5120 | Bhi 10240 | Blo 10240 = 30720; x2 stages
#define G2_STAGE 30720
#define G2_SMEM  (2 * G2_STAGE)

__global__ void __launch_bounds__(256, 2)
k_gemm2(float* __restrict__ out) {
    extern __shared__ __align__(16) uint8_t smem[];
    const uint32_t sb = smem_u32(smem);

    const int t = threadIdx.x;
    const int lane = t & 31, wid = t >> 5;
    const int warpM = wid >> 2, warpN = wid & 3;
    const int m0 = blockIdx.x * 64;

    const uint32_t aOff = (uint32_t)((lane & 15) * PITCH_B + (lane >> 4) * 16);
    const uint32_t bOff = (uint32_t)(((lane & 7) + ((lane >> 4) << 3)) * PITCH_B
                                     + ((lane >> 3) & 1) * 16);

    float acc[2][4][4];
    #pragma unroll
    for (int i = 0; i < 2; ++i)
        #pragma unroll
        for (int j = 0; j < 4; ++j)
            #pragma unroll
            for (int q = 0; q < 4; ++q) acc[i][j][q] = 0.f;

    auto prefetch = [&](int kc, int s) {
        const uint32_t base = sb + (uint32_t)s * G2_STAGE;
        {   // A: 64 rows x 32 k, hi/lo
            int row = t >> 2, c4 = t & 3;
            uint32_t d = (uint32_t)(row * PITCH_B + c4 * 16);
            size_t g = (size_t)(m0 + row) * NLEAF + kc * 32 + c4 * 8;
            cp16(base +        d, g_muh + g);
            cp16(base + 5120 + d, g_mul + g);
        }
        #pragma unroll
        for (int q = 0; q < 2; ++q) {       // B: 128 rows x 32 k, hi/lo
            int idx = q * 256 + t;
            int row = idx >> 2, c4 = idx & 3;
            uint32_t d = (uint32_t)(row * PITCH_B + c4 * 16);
            size_t g = (size_t)row * NLEAF + kc * 32 + c4 * 8;
            cp16(base + 10240 + d, g_ph + g);
            cp16(base + 20480 + d, g_pl + g);
        }
    };

    prefetch(0, 0);
    CP_COMMIT();

    for (int kc = 0; kc < 32; ++kc) {
        CP_WAIT0();
        __syncthreads();
        if (kc + 1 < 32) { prefetch(kc + 1, (kc + 1) & 1); CP_COMMIT(); }

        const uint32_t base = sb + (uint32_t)(kc & 1) * G2_STAGE;
        #pragma unroll
        for (int ks = 0; ks < 2; ++ks) {
            const uint32_t kb = ks * 32;
            #pragma unroll
            for (int pass = 0; pass < 3; ++pass) {
                const uint32_t uA = base + ((pass == 1) ? 5120u : 0u);
                const uint32_t uB = base + 10240u + ((pass == 2) ? 10240u : 0u);
                uint32_t a[2][4];
                #pragma unroll
                for (int mf = 0; mf < 2; ++mf)
                    ldsm4(a[mf], uA + (uint32_t)(warpM * 32 + mf * 16) * PITCH_B + aOff + kb);
                uint32_t b[2][4];
                #pragma unroll
                for (int p = 0; p < 2; ++p)
                    ldsm4(b[p], uB + (uint32_t)(warpN * 32 + p * 16) * PITCH_B + bOff + kb);
                #pragma unroll
                for (int mf = 0; mf < 2; ++mf)
                    #pragma unroll
                    for (int nf = 0; nf < 4; ++nf)
                        mma16816(acc[mf][nf], a[mf], &b[nf >> 1][(nf & 1) * 2]);
            }
        }
    }

    #pragma unroll
    for (int mf = 0; mf < 2; ++mf) {
        int row = m0 + warpM * 32 + mf * 16 + (lane >> 2);
        #pragma unroll
        for (int nf = 0; nf < 4; ++nf) {
            int col = warpN * 32 + nf * 8 + (lane & 3) * 2;
            if (col < NCLS) {
                float2 v0 = make_float2(acc[mf][nf][0], acc[mf][nf][1]);
                float2 v1 = make_float2(acc[mf][nf][2], acc[mf][nf][3]);
                *reinterpret_cast<float2*>(out + (size_t)row * NCLS + col) = v0;
                *reinterpret_cast<float2*>(out + (size_t)(row + 8) * NCLS + col) = v1;
            }
        }
    }
}

// ---------------- launch ----------------
extern "C" void kernel_launch(void* const* d_in, const int* in_sizes, int n_in,
                              void* d_out, int out_size) {
    const float* feat = (const float*)d_in[0];
    const float* mask = (const float*)d_in[1];
    const float* W    = (const float*)d_in[2];
    const float* b    = (const float*)d_in[3];
    const float* pi   = (const float*)d_in[4];
    float* out = (float*)d_out;
    (void)in_sizes; (void)n_in; (void)out_size;

    cudaFuncSetAttribute(k_gemm1, cudaFuncAttributeMaxDynamicSharedMemorySize, G1_SMEM);
    cudaFuncSetAttribute(k_gemm2, cudaFuncAttributeMaxDynamicSharedMemorySize, G2_SMEM);

    k_sel<<<1, 256>>>(mask);
    k_softmax<<<4, 256>>>(pi);
    k_wprep<<<(NLEAF * NUSED) / 256, 256>>>(W);
    k_gather<<<(BATCH * NUSED) / 512, 512>>>(feat);
    k_gemm1<<<dim3(BATCH / 128, NLEAF / 128), 256, G1_SMEM>>>(b);
    k_tree<<<BATCH / 8, 256>>>();
    k_gemm2<<<BATCH / 64, 256, G2_SMEM>>>(out);
}

// round 7
// speedup vs baseline: 2.8298x; 1.1709x over previous
#include <cuda_runtime.h>
#include <cuda_bf16.h>
#include <cstdint>
#include <cstddef>

#define BATCH 16384
#define NFEAT 512
#define NUSED 256
#define NLEAF 1024
#define NCLS  100
#define NCLSP 128

// ---------------- device scratch ----------------
__device__ int   g_sel[NUSED];
__device__ float g_d[(size_t)BATCH * NLEAF];                  // fp32 d (tree input)
__device__ __nv_bfloat16 g_xh[(size_t)BATCH * NUSED];         // x hi
__device__ __nv_bfloat16 g_xl[(size_t)BATCH * NUSED];         // x lo
__device__ __nv_bfloat16 g_wh[NLEAF * NUSED];                 // W^T hi  [n][k]
__device__ __nv_bfloat16 g_wl[NLEAF * NUSED];                 // W^T lo
__device__ __nv_bfloat16 g_muh[(size_t)BATCH * NLEAF];        // mu hi (lo dropped)
__device__ __nv_bfloat16 g_ph[NCLSP * NLEAF];                 // probs^T hi [c][L]
__device__ __nv_bfloat16 g_pl[NCLSP * NLEAF];                 // probs^T lo

// ---------------- helpers ----------------
__device__ __forceinline__ uint32_t smem_u32(const void* p) {
    uint32_t a;
    asm("{ .reg .u64 t; cvta.to.shared.u64 t, %1; cvt.u32.u64 %0, t; }" : "=r"(a) : "l"(p));
    return a;
}
__device__ __forceinline__ void ldsm4(uint32_t r[4], uint32_t addr) {
    asm volatile("ldmatrix.sync.aligned.m8n8.x4.shared.b16 {%0,%1,%2,%3}, [%4];"
                 : "=r"(r[0]), "=r"(r[1]), "=r"(r[2]), "=r"(r[3]) : "r"(addr));
}
__device__ __forceinline__ void mma16816(float c[4], const uint32_t a[4], const uint32_t b[2]) {
    asm volatile("mma.sync.aligned.m16n8k16.row.col.f32.bf16.bf16.f32 "
                 "{%0,%1,%2,%3}, {%4,%5,%6,%7}, {%8,%9}, {%0,%1,%2,%3};"
                 : "+f"(c[0]), "+f"(c[1]), "+f"(c[2]), "+f"(c[3])
                 : "r"(a[0]), "r"(a[1]), "r"(a[2]), "r"(a[3]), "r"(b[0]), "r"(b[1]));
}
__device__ __forceinline__ void cp16(uint32_t smem_dst, const void* gptr) {
    asm volatile("cp.async.cg.shared.global [%0], [%1], 16;"
                 :: "r"(smem_dst), "l"(gptr));
}
#define CP_COMMIT() asm volatile("cp.async.commit_group;" ::: "memory")
#define CP_WAIT0()  asm volatile("cp.async.wait_group 0;" ::: "memory")

__device__ __forceinline__ float sigm(float z) { return 1.f / (1.f + __expf(-z)); }

// smem tile pitch: 40 bf16 = 80 B (5 x 16B -> conflict-free ldmatrix phases)
#define PITCH_B 80

// ---------------- prep ----------------
__global__ void k_sel(const float* __restrict__ mask) {
    int j = threadIdx.x;
    if (j < NUSED) {
        const float* row = mask + j * NFEAT;
        int s = 0;
        for (int f = 0; f < NFEAT; ++f) if (row[f] > 0.5f) { s = f; break; }
        g_sel[j] = s;
    }
}

// blocks [0,4): softmax | [4,1028): wprep | [1028,17412): gather
#define PREP_SM 4
#define PREP_WP (PREP_SM + 1024)
#define PREP_GA (PREP_WP + (BATCH * NUSED) / 256)

__global__ void __launch_bounds__(256)
k_prep(const float* __restrict__ pi, const float* __restrict__ W,
       const float* __restrict__ feat) {
    const int bb = blockIdx.x;
    const int t = threadIdx.x;
    if (bb < PREP_SM) {
        int r = bb * 256 + t;
        const float* p = pi + r * NCLS;
        float mx = p[0];
        for (int c = 1; c < NCLS; ++c) mx = fmaxf(mx, p[c]);
        float s = 0.f;
        for (int c = 0; c < NCLS; ++c) s += expf(p[c] - mx);
        float inv = 1.f / s;
        for (int c = 0; c < NCLS; ++c) {
            float v = expf(p[c] - mx) * inv;
            __nv_bfloat16 hi = __float2bfloat16(v);
            __nv_bfloat16 lo = __float2bfloat16(v - __bfloat162float(hi));
            g_ph[c * NLEAF + r] = hi;
            g_pl[c * NLEAF + r] = lo;
        }
        for (int c = NCLS; c < NCLSP; ++c) {
            g_ph[c * NLEAF + r] = __float2bfloat16(0.f);
            g_pl[c * NLEAF + r] = __float2bfloat16(0.f);
        }
    } else if (bb < PREP_WP) {
        int idx = (bb - PREP_SM) * 256 + t;
        int n = idx >> 8, k = idx & 255;
        float v = W[(size_t)k * NLEAF + n];
        __nv_bfloat16 hi = __float2bfloat16(v);
        __nv_bfloat16 lo = __float2bfloat16(v - __bfloat162float(hi));
        g_wh[n * NUSED + k] = hi;
        g_wl[n * NUSED + k] = lo;
    } else {
        int i = (bb - PREP_WP) * 256 + t;
        int row = i >> 8, j = i & 255;
        float v = feat[(size_t)row * NFEAT + g_sel[j]];
        __nv_bfloat16 hi = __float2bfloat16(v);
        __nv_bfloat16 lo = __float2bfloat16(v - __bfloat162float(hi));
        g_xh[i] = hi;
        g_xl[i] = lo;
    }
}

// ---------------- GEMM1: d = sigmoid(x @ W + b), 3-pass bf16 ----------------
// block 128x128, 8 warps (2M x 4N), warp 64x32, K-chunks of 32, double buffer
#define G1_STAGE 40960
#define G1_SMEM  (2 * G1_STAGE)

__global__ void __launch_bounds__(256, 2)
k_gemm1(const float* __restrict__ bias) {
    extern __shared__ __align__(16) uint8_t smem[];
    const uint32_t sb = smem_u32(smem);

    const int t = threadIdx.x;
    const int lane = t & 31, wid = t >> 5;
    const int warpM = wid >> 2, warpN = wid & 3;
    const int m0 = blockIdx.x * 128;
    const int n0 = blockIdx.y * 128;

    const uint32_t aOff = (uint32_t)((lane & 15) * PITCH_B + (lane >> 4) * 16);
    const uint32_t bOff = (uint32_t)(((lane & 7) + ((lane >> 4) << 3)) * PITCH_B
                                     + ((lane >> 3) & 1) * 16);

    float acc[4][4][4];
    #pragma unroll
    for (int i = 0; i < 4; ++i)
        #pragma unroll
        for (int j = 0; j < 4; ++j)
            #pragma unroll
            for (int q = 0; q < 4; ++q) acc[i][j][q] = 0.f;

    auto prefetch = [&](int kc, int s) {
        const uint32_t base = sb + (uint32_t)s * G1_STAGE;
        #pragma unroll
        for (int q = 0; q < 2; ++q) {
            int idx = q * 256 + t;
            int row = idx >> 2, c4 = idx & 3;
            uint32_t d = (uint32_t)(row * PITCH_B + c4 * 16);
            size_t ga = (size_t)(m0 + row) * NUSED + kc * 32 + c4 * 8;
            cp16(base +         d, g_xh + ga);
            cp16(base + 10240 + d, g_xl + ga);
            size_t gb = (size_t)(n0 + row) * NUSED + kc * 32 + c4 * 8;
            cp16(base + 20480 + d, g_wh + gb);
            cp16(base + 30720 + d, g_wl + gb);
        }
    };

    prefetch(0, 0);
    CP_COMMIT();

    for (int kc = 0; kc < 8; ++kc) {
        CP_WAIT0();
        __syncthreads();
        if (kc + 1 < 8) { prefetch(kc + 1, (kc + 1) & 1); CP_COMMIT(); }

        const uint32_t base = sb + (uint32_t)(kc & 1) * G1_STAGE;
        const uint32_t uAhi = base, uAlo = base + 10240u;
        const uint32_t uBhi = base + 20480u, uBlo = base + 30720u;

        #pragma unroll
        for (int ks = 0; ks < 2; ++ks) {
            const uint32_t kb = ks * 32;
            uint32_t a[4][4], b[2][4];
            // pass 1: Ahi x Bhi
            #pragma unroll
            for (int mf = 0; mf < 4; ++mf)
                ldsm4(a[mf], uAhi + (uint32_t)(warpM * 64 + mf * 16) * PITCH_B + aOff + kb);
            #pragma unroll
            for (int p = 0; p < 2; ++p)
                ldsm4(b[p], uBhi + (uint32_t)(warpN * 32 + p * 16) * PITCH_B + bOff + kb);
            #pragma unroll
            for (int mf = 0; mf < 4; ++mf)
                #pragma unroll
                for (int nf = 0; nf < 4; ++nf)
                    mma16816(acc[mf][nf], a[mf], &b[nf >> 1][(nf & 1) * 2]);
            // pass 2: Ahi x Blo (A reused)
            #pragma unroll
            for (int p = 0; p < 2; ++p)
                ldsm4(b[p], uBlo + (uint32_t)(warpN * 32 + p * 16) * PITCH_B + bOff + kb);
            #pragma unroll
            for (int mf = 0; mf < 4; ++mf)
                #pragma unroll
                for (int nf = 0; nf < 4; ++nf)
                    mma16816(acc[mf][nf], a[mf], &b[nf >> 1][(nf & 1) * 2]);
            // pass 3: Alo x Bhi
            #pragma unroll
            for (int mf = 0; mf < 4; ++mf)
                ldsm4(a[mf], uAlo + (uint32_t)(warpM * 64 + mf * 16) * PITCH_B + aOff + kb);
            #pragma unroll
            for (int p = 0; p < 2; ++p)
                ldsm4(b[p], uBhi + (uint32_t)(warpN * 32 + p * 16) * PITCH_B + bOff + kb);
            #pragma unroll
            for (int mf = 0; mf < 4; ++mf)
                #pragma unroll
                for (int nf = 0; nf < 4; ++nf)
                    mma16816(acc[mf][nf], a[mf], &b[nf >> 1][(nf & 1) * 2]);
        }
    }

    // epilogue: bias + sigmoid -> g_d (fp32)
    #pragma unroll
    for (int mf = 0; mf < 4; ++mf) {
        int row = m0 + warpM * 64 + mf * 16 + (lane >> 2);
        #pragma unroll
        for (int nf = 0; nf < 4; ++nf) {
            int col = n0 + warpN * 32 + nf * 8 + (lane & 3) * 2;
            float2 bb = *reinterpret_cast<const float2*>(bias + col);
            float2 v0, v1;
            v0.x = sigm(acc[mf][nf][0] + bb.x);
            v0.y = sigm(acc[mf][nf][1] + bb.y);
            v1.x = sigm(acc[mf][nf][2] + bb.x);
            v1.y = sigm(acc[mf][nf][3] + bb.y);
            *reinterpret_cast<float2*>(g_d + (size_t)row * NLEAF + col) = v0;
            *reinterpret_cast<float2*>(g_d + (size_t)(row + 8) * NLEAF + col) = v1;
        }
    }
}

// ---------------- tree: mu hi (bf16) from d, 4-leaf groups ----------------
__global__ void __launch_bounds__(256) k_tree() {
    __shared__ float ds[8][NLEAF];
    const int t = threadIdx.x;
    const size_t base = (size_t)blockIdx.x * 8 * NLEAF;

    const float4* src = reinterpret_cast<const float4*>(g_d + base);
    float4* s4 = reinterpret_cast<float4*>(&ds[0][0]);
    #pragma unroll
    for (int q = 0; q < 8; ++q) s4[q * 256 + t] = src[q * 256 + t];
    __syncthreads();

    const int r  = t >> 5;
    const int l0 = t & 31;
    const float* dr = ds[r];
    const size_t ob = base + (size_t)r * NLEAF;

    #pragma unroll
    for (int i = 0; i < 8; ++i) {
        int g = i * 32 + l0;
        int L0 = g * 4;
        float p = 1.f;
        #pragma unroll
        for (int k = 0; k < 8; ++k) {
            int node = (1 << k) + (L0 >> (10 - k));
            float v  = dr[node];
            p *= ((L0 >> (9 - k)) & 1) ? (1.f - v) : v;
        }
        float v8  = dr[256 + (L0 >> 2)];
        float v9a = dr[512 + (L0 >> 1)];
        float v9b = dr[512 + (L0 >> 1) + 1];
        float pv8 = p * v8;
        float pn8 = p - pv8;
        float m0 = pv8 * v9a;
        float m1 = pv8 - m0;
        float m2 = pn8 * v9b;
        float m3 = pn8 - m2;

        __nv_bfloat162 hp0 = __nv_bfloat162(__float2bfloat16(m0), __float2bfloat16(m1));
        __nv_bfloat162 hp1 = __nv_bfloat162(__float2bfloat16(m2), __float2bfloat16(m3));
        uint2 hu;
        hu.x = *reinterpret_cast<uint32_t*>(&hp0);
        hu.y = *reinterpret_cast<uint32_t*>(&hp1);
        *reinterpret_cast<uint2*>(g_muh + ob + L0) = hu;
    }
}

// ---------------- GEMM2: out = mu_hi @ (p_hi + p_lo), 2-pass ----------------
// block 64x128, 8 warps (2M x 4N), warp 32x32, K-chunks of 32, double buffer
// stage: Ahi 5120 | Bhi 10240 | Blo 10240 = 25600
#define G2_STAGE 25600
#define G2_SMEM  (2 * G2_STAGE)

__global__ void __launch_bounds__(256, 2)
k_gemm2(float* __restrict__ out) {
    extern __shared__ __align__(16) uint8_t smem[];
    const uint32_t sb = smem_u32(smem);

    const int t = threadIdx.x;
    const int lane = t & 31, wid = t >> 5;
    const int warpM = wid >> 2, warpN = wid & 3;
    const int m0 = blockIdx.x * 64;

    const uint32_t aOff = (uint32_t)((lane & 15) * PITCH_B + (lane >> 4) * 16);
    const uint32_t bOff = (uint32_t)(((lane & 7) + ((lane >> 4) << 3)) * PITCH_B
                                     + ((lane >> 3) & 1) * 16);

    float acc[2][4][4];
    #pragma unroll
    for (int i = 0; i < 2; ++i)
        #pragma unroll
        for (int j = 0; j < 4; ++j)
            #pragma unroll
            for (int q = 0; q < 4; ++q) acc[i][j][q] = 0.f;

    auto prefetch = [&](int kc, int s) {
        const uint32_t base = sb + (uint32_t)s * G2_STAGE;
        {   // A hi: 64 rows x 32 k
            int row = t >> 2, c4 = t & 3;
            uint32_t d = (uint32_t)(row * PITCH_B + c4 * 16);
            size_t g = (size_t)(m0 + row) * NLEAF + kc * 32 + c4 * 8;
            cp16(base + d, g_muh + g);
        }
        #pragma unroll
        for (int q = 0; q < 2; ++q) {       // B hi/lo: 128 rows x 32 k
            int idx = q * 256 + t;
            int row = idx >> 2, c4 = idx & 3;
            uint32_t d = (uint32_t)(row * PITCH_B + c4 * 16);
            size_t g = (size_t)row * NLEAF + kc * 32 + c4 * 8;
            cp16(base +  5120 + d, g_ph + g);
            cp16(base + 15360 + d, g_pl + g);
        }
    };

    prefetch(0, 0);
    CP_COMMIT();

    for (int kc = 0; kc < 32; ++kc) {
        CP_WAIT0();
        __syncthreads();
        if (kc + 1 < 32) { prefetch(kc + 1, (kc + 1) & 1); CP_COMMIT(); }

        const uint32_t base = sb + (uint32_t)(kc & 1) * G2_STAGE;
        const uint32_t uA = base, uBhi = base + 5120u, uBlo = base + 15360u;

        #pragma unroll
        for (int ks = 0; ks < 2; ++ks) {
            const uint32_t kb = ks * 32;
            uint32_t a[2][4], b[2][4];
            #pragma unroll
            for (int mf = 0; mf < 2; ++mf)
                ldsm4(a[mf], uA + (uint32_t)(warpM * 32 + mf * 16) * PITCH_B + aOff + kb);
            // pass 1: A x Bhi
            #pragma unroll
            for (int p = 0; p < 2; ++p)
                ldsm4(b[p], uBhi + (uint32_t)(warpN * 32 + p * 16) * PITCH_B + bOff + kb);
            #pragma unroll
            for (int mf = 0; mf < 2; ++mf)
                #pragma unroll
                for (int nf = 0; nf < 4; ++nf)
                    mma16816(acc[mf][nf], a[mf], &b[nf >> 1][(nf & 1) * 2]);
            // pass 2: A x Blo (A reused)
            #pragma unroll
            for (int p = 0; p < 2; ++p)
                ldsm4(b[p], uBlo + (uint32_t)(warpN * 32 + p * 16) * PITCH_B + bOff + kb);
            #pragma unroll
            for (int mf = 0; mf < 2; ++mf)
                #pragma unroll
                for (int nf = 0; nf < 4; ++nf)
                    mma16816(acc[mf][nf], a[mf], &b[nf >> 1][(nf & 1) * 2]);
        }
    }

    #pragma unroll
    for (int mf = 0; mf < 2; ++mf) {
        int row = m0 + warpM * 32 + mf * 16 + (lane >> 2);
        #pragma unroll
        for (int nf = 0; nf < 4; ++nf) {
            int col = warpN * 32 + nf * 8 + (lane & 3) * 2;
            if (col < NCLS) {
                float2 v0 = make_float2(acc[mf][nf][0], acc[mf][nf][1]);
                float2 v1 = make_float2(acc[mf][nf][2], acc[mf][nf][3]);
                *reinterpret_cast<float2*>(out + (size_t)row * NCLS + col) = v0;
                *reinterpret_cast<float2*>(out + (size_t)(row + 8) * NCLS + col) = v1;
            }
        }
    }
}

// ---------------- launch ----------------
extern "C" void kernel_launch(void* const* d_in, const int* in_sizes, int n_in,
                              void* d_out, int out_size) {
    const float* feat = (const float*)d_in[0];
    const float* mask = (const float*)d_in[1];
    const float* W    = (const float*)d_in[2];
    const float* b    = (const float*)d_in[3];
    const float* pi   = (const float*)d_in[4];
    float* out = (float*)d_out;
    (void)in_sizes; (void)n_in; (void)out_size;

    cudaFuncSetAttribute(k_gemm1, cudaFuncAttributeMaxDynamicSharedMemorySize, G1_SMEM);
    cudaFuncSetAttribute(k_gemm2, cudaFuncAttributeMaxDynamicSharedMemorySize, G2_SMEM);

    k_sel<<<1, 256>>>(mask);
    k_prep<<<PREP_GA, 256>>>(pi, W, feat);
    k_gemm1<<<dim3(BATCH / 128, NLEAF / 128), 256, G1_SMEM>>>(b);
    k_tree<<<BATCH / 8, 256>>>();
    k_gemm2<<<BATCH / 64, 256, G2_SMEM>>>(out);
}